// round 5
// baseline (speedup 1.0000x reference)
#include <cuda_runtime.h>
#include <cuda_bf16.h>
#include <cstdint>

#define N_NODES   100000
#define NODE_PAD  100096            // 782 * 128
#define N_EDGES   1000000
#define N_GRAPHS  1024
#define SCAN_BLK  512
#define N_SCAN_BLKS ((N_NODES + SCAN_BLK - 1) / SCAN_BLK)   // 196
#define EB ((N_EDGES + 255) / 256)  // edge blocks in prologue
#define NB ((N_NODES + 255) / 256)  // node blocks in prologue

// ---------------- scratch (device globals; zero-initialized at load) --------
// Invariants maintained across calls:
//  - g_deg is zero on entry (BSS at load; fill_kernel re-zeroes after last use)
//  - g_sstate is zeroed by prologue block 0 each call, before the scan runs
__device__ __align__(16) float g_h0  [NODE_PAD * 32];
__device__ __align__(16) float g_h1  [NODE_PAD * 64];
__device__ __align__(16) float g_h2  [NODE_PAD * 64];
__device__ int g_deg[N_NODES];
__device__ int g_off[N_NODES + 1];
__device__ int g_cur[N_NODES];
__device__ int g_eidx[N_EDGES];
__device__ unsigned long long g_sstate[N_SCAN_BLKS];
__device__ int g_gstart[N_GRAPHS + 1];

// ---------------- fused prologue: edge count | bounds + node embed ----------
__global__ void __launch_bounds__(256) prologue_kernel(
    const int* __restrict__ dst,
    const int* __restrict__ batch,
    const int* __restrict__ x,
    const float* __restrict__ shape_emb,
    const float* __restrict__ color_emb,
    const float* __restrict__ W_node,
    const float* __restrict__ b_node)
{
    int tid = threadIdx.x;
    if (blockIdx.x < EB) {
        // role 1: degree count (+ block 0 resets scan state for this call)
        if (blockIdx.x == 0 && tid < N_SCAN_BLKS) g_sstate[tid] = 0ULL;
        int e = blockIdx.x * 256 + tid;
        if (e < N_EDGES) atomicAdd(&g_deg[dst[e]], 1);
        return;
    }
    // role 2: graph bounds + node embedding
    int n = (blockIdx.x - EB) * 256 + tid;

    __shared__ float sW[16 * 32];
    __shared__ float sb[32];
    __shared__ float sS[64];
    __shared__ float sC[64];
    for (int i = tid; i < 16 * 32; i += 256) sW[i] = W_node[i];
    if (tid < 32) sb[tid] = b_node[tid];
    if (tid < 64) { sS[tid] = shape_emb[tid]; sC[tid] = color_emb[tid]; }
    __syncthreads();

    if (n >= N_NODES) return;

    // bounds (batch is sorted)
    {
        int b1 = batch[n];
        int b0 = (n == 0) ? -1 : batch[n - 1];
        for (int g = b0 + 1; g <= b1; g++) g_gstart[g] = n;
        if (n == N_NODES - 1)
            for (int g = b1 + 1; g <= N_GRAPHS; g++) g_gstart[g] = N_NODES;
    }

    // embedding
    int sh = x[2 * n];
    int co = x[2 * n + 1];
    float acc[32];
#pragma unroll
    for (int j = 0; j < 32; j++) acc[j] = sb[j];
#pragma unroll
    for (int k = 0; k < 8; k++) {
        float s = sS[sh * 8 + k];
        float c = sC[co * 8 + k];
#pragma unroll
        for (int j = 0; j < 32; j++)
            acc[j] += s * sW[k * 32 + j] + c * sW[(8 + k) * 32 + j];
    }
    float4* out = (float4*)&g_h0[(size_t)n * 32];
#pragma unroll
    for (int q = 0; q < 8; q++) {
        float4 v;
        v.x = fmaxf(acc[q * 4 + 0], 0.f);
        v.y = fmaxf(acc[q * 4 + 1], 0.f);
        v.z = fmaxf(acc[q * 4 + 2], 0.f);
        v.w = fmaxf(acc[q * 4 + 3], 0.f);
        out[q] = v;
    }
}

// ---------------- single-pass scan (decoupled lookback) ---------------------
// g_sstate[b] = (value << 2) | flag;  flag: 0=empty, 1=aggregate, 2=prefix.
// Flag and value live in one 64-bit word -> single atomic, no fences needed.
__global__ void __launch_bounds__(SCAN_BLK) scan_kernel() {
    __shared__ int s[SCAN_BLK];
    __shared__ int sprefix;
    int bid = blockIdx.x, tid = threadIdx.x;
    int n = bid * SCAN_BLK + tid;
    int d = (n < N_NODES) ? g_deg[n] : 0;
    s[tid] = d;
    __syncthreads();
    for (int off = 1; off < SCAN_BLK; off <<= 1) {
        int v = (tid >= off) ? s[tid - off] : 0;
        __syncthreads();
        s[tid] += v;
        __syncthreads();
    }
    int agg = s[SCAN_BLK - 1];

    if (tid == 0) {
        if (bid == 0) {
            atomicExch(&g_sstate[0], ((unsigned long long)agg << 2) | 2ULL);
            sprefix = 0;
        } else {
            atomicExch(&g_sstate[bid], ((unsigned long long)agg << 2) | 1ULL);
            long long ex = 0;
            int p = bid - 1;
            for (;;) {
                unsigned long long v;
                do { v = atomicOr(&g_sstate[p], 0ULL); } while ((v & 3ULL) == 0ULL);
                ex += (long long)(v >> 2);
                if ((v & 3ULL) == 2ULL) break;
                p--;
            }
            atomicExch(&g_sstate[bid],
                       ((unsigned long long)(ex + agg) << 2) | 2ULL);
            sprefix = (int)ex;
        }
    }
    __syncthreads();
    int pre = sprefix;
    if (n < N_NODES) {
        int o = pre + s[tid] - d;   // exclusive
        g_off[n] = o;
        g_cur[n] = o;
    }
    if (bid == N_SCAN_BLKS - 1 && tid == SCAN_BLK - 1)
        g_off[N_NODES] = pre + agg;
}

// fill CSR; also restore the g_deg==0 invariant for the next call
__global__ void fill_kernel(const int* __restrict__ src, const int* __restrict__ dst) {
    int e = blockIdx.x * blockDim.x + threadIdx.x;
    if (e < N_NODES) g_deg[e] = 0;
    if (e >= N_EDGES) return;
    int d = dst[e];
    int pos = atomicAdd(&g_cur[d], 1);
    g_eidx[pos] = src[e];
}

// ---------------- fused gather + tf32 conv ----------------------------------
// Per block: 128 nodes. Phase 1: warp-per-node CSR gather into smem sA.
// Phase 2: hout = relu([sA | hin] @ [Wrel;Wroot] + b) via m16n8k8 tf32 MMA.
// sA stride KIN+4 => A-frag LDS banks = 4*r4 + c4 (conflict-free).
// sW stride 72   => B-frag LDS banks = 8*c4 + r4 (conflict-free).
__device__ __forceinline__ uint32_t f2tf32(float f) {
    uint32_t u;
    asm("cvt.rna.tf32.f32 %0, %1;" : "=r"(u) : "f"(f));
    return u;
}

__device__ __forceinline__ void mma_tf32(float c[4],
                                         uint32_t a0, uint32_t a1, uint32_t a2, uint32_t a3,
                                         uint32_t b0, uint32_t b1) {
    asm volatile(
        "mma.sync.aligned.m16n8k8.row.col.f32.tf32.tf32.f32 "
        "{%0,%1,%2,%3}, {%4,%5,%6,%7}, {%8,%9}, {%0,%1,%2,%3};"
        : "+f"(c[0]), "+f"(c[1]), "+f"(c[2]), "+f"(c[3])
        : "r"(a0), "r"(a1), "r"(a2), "r"(a3), "r"(b0), "r"(b1));
}

template <int KIN, bool L1>
__global__ void __launch_bounds__(256) gatherconv_kernel(
    const float* __restrict__ Wrel,
    const float* __restrict__ Wroot,
    const float* __restrict__ b)
{
    const float* hin  = L1 ? g_h0 : g_h1;
    float*       hout = L1 ? g_h1 : g_h2;

    constexpr int K2 = 2 * KIN;
    constexpr int STEPS = K2 / 8;
    constexpr int LDB = 72;
    constexpr int SAS = KIN + 4;

    extern __shared__ char smem[];
    uint32_t* sW = (uint32_t*)smem;                    // K2 * LDB
    float*    sb = (float*)(smem + (size_t)K2 * LDB * 4);  // 64
    float*    sA = sb + 64;                            // 128 * SAS

    int tid = threadIdx.x;
    int lane = tid & 31, wid = tid >> 5;
    int base = blockIdx.x * 128;

    // weights -> smem (tf32 bits)
    for (int i = tid; i < K2 * 64; i += 256) {
        int k = i >> 6, n = i & 63;
        float v = (k < KIN) ? Wrel[k * 64 + n] : Wroot[(k - KIN) * 64 + n];
        sW[k * LDB + n] = f2tf32(v);
    }
    if (tid < 64) sb[tid] = b[tid];

    // ---- phase 1: gather (warp per node, 16 nodes per warp) ----
    for (int j = 0; j < 16; j++) {
        int nl = wid * 16 + j;
        int node = base + nl;
        if (node >= N_NODES) {
            if (KIN == 32) {
                sA[nl * SAS + lane] = 0.f;
            } else {
                sA[nl * SAS + 2 * lane]     = 0.f;
                sA[nl * SAS + 2 * lane + 1] = 0.f;
            }
            continue;
        }
        int s0 = g_off[node], s1 = g_off[node + 1];
        if (KIN == 32) {
            float acc = 0.f;
            int i = s0;
            for (; i + 3 < s1; i += 4) {
                int sa = __ldg(&g_eidx[i]);
                int sbb = __ldg(&g_eidx[i + 1]);
                int sc = __ldg(&g_eidx[i + 2]);
                int sd = __ldg(&g_eidx[i + 3]);
                float va = hin[(size_t)sa * 32 + lane];
                float vb = hin[(size_t)sbb * 32 + lane];
                float vc = hin[(size_t)sc * 32 + lane];
                float vd = hin[(size_t)sd * 32 + lane];
                acc += (va + vb) + (vc + vd);
            }
            for (; i < s1; i++)
                acc += hin[(size_t)__ldg(&g_eidx[i]) * 32 + lane];
            sA[nl * SAS + lane] = acc;
        } else {
            float ax = 0.f, ay = 0.f;
            int i = s0;
            for (; i + 3 < s1; i += 4) {
                int sa = __ldg(&g_eidx[i]);
                int sbb = __ldg(&g_eidx[i + 1]);
                int sc = __ldg(&g_eidx[i + 2]);
                int sd = __ldg(&g_eidx[i + 3]);
                float2 va = ((const float2*)hin)[(size_t)sa * 32 + lane];
                float2 vb = ((const float2*)hin)[(size_t)sbb * 32 + lane];
                float2 vc = ((const float2*)hin)[(size_t)sc * 32 + lane];
                float2 vd = ((const float2*)hin)[(size_t)sd * 32 + lane];
                ax += (va.x + vb.x) + (vc.x + vd.x);
                ay += (va.y + vb.y) + (vc.y + vd.y);
            }
            for (; i < s1; i++) {
                float2 va = ((const float2*)hin)[(size_t)__ldg(&g_eidx[i]) * 32 + lane];
                ax += va.x;
                ay += va.y;
            }
            sA[nl * SAS + 2 * lane]     = ax;
            sA[nl * SAS + 2 * lane + 1] = ay;
        }
    }
    __syncthreads();

    // ---- phase 2: MMA ----
    int wm = wid >> 1, wn = wid & 1;
    int r4 = lane >> 2, c4 = lane & 3;
    int nl0 = wm * 32 + r4;

    float acc[2][4][4];
#pragma unroll
    for (int t = 0; t < 2; t++)
#pragma unroll
        for (int u = 0; u < 4; u++) {
            int col = wn * 32 + u * 8 + c4 * 2;
            acc[t][u][0] = sb[col];
            acc[t][u][1] = sb[col + 1];
            acc[t][u][2] = sb[col];
            acc[t][u][3] = sb[col + 1];
        }

#pragma unroll
    for (int s = 0; s < STEPS; s++) {
        uint32_t a[2][4];
        if (s * 8 < KIN) {
            int koff = s * 8 + c4;
#pragma unroll
            for (int t = 0; t < 2; t++) {
                const float* p0 = sA + (nl0 + t * 16) * SAS + koff;
                const float* p8 = sA + (nl0 + t * 16 + 8) * SAS + koff;
                a[t][0] = f2tf32(p0[0]);
                a[t][1] = f2tf32(p8[0]);
                a[t][2] = f2tf32(p0[4]);
                a[t][3] = f2tf32(p8[4]);
            }
        } else {
            int koff = s * 8 - KIN + c4;
#pragma unroll
            for (int t = 0; t < 2; t++) {
                const float* row0 = hin + (size_t)(base + nl0 + t * 16) * KIN + koff;
                const float* row8 = hin + (size_t)(base + nl0 + t * 16 + 8) * KIN + koff;
                a[t][0] = f2tf32(__ldg(row0));
                a[t][1] = f2tf32(__ldg(row8));
                a[t][2] = f2tf32(__ldg(row0 + 4));
                a[t][3] = f2tf32(__ldg(row8 + 4));
            }
        }

        int krow = s * 8 + c4;
        uint32_t bf[4][2];
#pragma unroll
        for (int u = 0; u < 4; u++) {
            int col = wn * 32 + u * 8 + r4;
            bf[u][0] = sW[krow * LDB + col];
            bf[u][1] = sW[(krow + 4) * LDB + col];
        }

#pragma unroll
        for (int t = 0; t < 2; t++)
#pragma unroll
            for (int u = 0; u < 4; u++)
                mma_tf32(acc[t][u], a[t][0], a[t][1], a[t][2], a[t][3],
                         bf[u][0], bf[u][1]);
    }

#pragma unroll
    for (int t = 0; t < 2; t++) {
        int row = base + wm * 32 + t * 16 + r4;
#pragma unroll
        for (int u = 0; u < 4; u++) {
            int col = wn * 32 + u * 8 + c4 * 2;
            float2 lo = make_float2(fmaxf(acc[t][u][0], 0.f), fmaxf(acc[t][u][1], 0.f));
            float2 hi = make_float2(fmaxf(acc[t][u][2], 0.f), fmaxf(acc[t][u][3], 0.f));
            *(float2*)&hout[(size_t)row * 64 + col]       = lo;
            *(float2*)&hout[(size_t)(row + 8) * 64 + col] = hi;
        }
    }
}

// ---------------- fused mean-pool + classifier ------------------------------
__global__ void __launch_bounds__(64) poolcls_kernel(
    const float* __restrict__ W_cls,
    const float* __restrict__ b_cls,
    float* __restrict__ out)
{
    int g = blockIdx.x;
    int tid = threadIdx.x;
    int s = g_gstart[g], e = g_gstart[g + 1];
    float acc = 0.f;
    for (int n = s; n < e; n++) acc += g_h2[(size_t)n * 64 + tid];
    float cnt = fmaxf((float)(e - s), 1.0f);
    __shared__ float sp[64];
    sp[tid] = acc / cnt;
    __syncthreads();
    if (tid < 10) {
        float dot = b_cls[tid];
#pragma unroll 8
        for (int k = 0; k < 64; k++) dot += sp[k] * W_cls[k * 10 + tid];
        out[(size_t)g * 10 + tid] = dot;
    }
}

// ---------------- launch ------------------------------------------------------
extern "C" void kernel_launch(void* const* d_in, const int* in_sizes, int n_in,
                              void* d_out, int out_size)
{
    const int*   x         = (const int*)  d_in[0];
    const int*   edge_index= (const int*)  d_in[1];
    const int*   batch     = (const int*)  d_in[2];
    const float* shape_emb = (const float*)d_in[3];
    const float* color_emb = (const float*)d_in[4];
    const float* W_node    = (const float*)d_in[5];
    const float* b_node    = (const float*)d_in[6];
    const float* W1_rel    = (const float*)d_in[7];
    const float* W1_root   = (const float*)d_in[8];
    const float* b1        = (const float*)d_in[9];
    const float* W2_rel    = (const float*)d_in[10];
    const float* W2_root   = (const float*)d_in[11];
    const float* b2        = (const float*)d_in[12];
    const float* W_cls     = (const float*)d_in[13];
    const float* b_cls     = (const float*)d_in[14];
    float* out = (float*)d_out;

    const int* src = edge_index;            // edge_index[0, :]
    const int* dst = edge_index + N_EDGES;  // edge_index[1, :]

    // dynamic smem sizes: sW(K2*72*4) + sb(64*4) + sA(128*(KIN+4)*4)
    const int smem32 = 64 * 72 * 4 + 64 * 4 + 128 * 36 * 4;    // ~37 KB
    const int smem64 = 128 * 72 * 4 + 64 * 4 + 128 * 68 * 4;   // ~72 KB
    cudaFuncSetAttribute(gatherconv_kernel<32, true>,
                         cudaFuncAttributeMaxDynamicSharedMemorySize, smem32);
    cudaFuncSetAttribute(gatherconv_kernel<64, false>,
                         cudaFuncAttributeMaxDynamicSharedMemorySize, smem64);

    prologue_kernel<<<EB + NB, 256>>>(dst, batch, x, shape_emb, color_emb, W_node, b_node);
    scan_kernel<<<N_SCAN_BLKS, SCAN_BLK>>>();
    fill_kernel<<<(N_EDGES + 255) / 256, 256>>>(src, dst);

    gatherconv_kernel<32, true><<<NODE_PAD / 128, 256, smem32>>>(W1_rel, W1_root, b1);
    gatherconv_kernel<64, false><<<NODE_PAD / 128, 256, smem64>>>(W2_rel, W2_root, b2);

    poolcls_kernel<<<N_GRAPHS, 64>>>(W_cls, b_cls, out);
}

// round 6
// speedup vs baseline: 1.1712x; 1.1712x over previous
#include <cuda_runtime.h>
#include <cuda_bf16.h>
#include <cstdint>

#define N_NODES   100000
#define NODE_PAD  100096            // 782 * 128
#define N_EDGES   1000000
#define N_GRAPHS  1024
#define SCAN_BLK  512
#define N_SCAN_BLKS ((N_NODES + SCAN_BLK - 1) / SCAN_BLK)   // 196
#define EB ((N_EDGES + 255) / 256)  // edge blocks in prologue
#define NB ((N_NODES + 255) / 256)  // node blocks in prologue

// ---------------- scratch (device globals; zero-initialized at load) --------
// Invariants across calls:
//  - g_deg is zero on entry (BSS at load; fill_kernel re-zeroes after last use)
//  - g_sstate is zeroed by prologue block 0 each call, before the scan runs
//  - pad rows (>= N_NODES) of g_h0/g_agg0/g_agg1 are never written, stay zero
__device__ __align__(16) float g_h0  [NODE_PAD * 32];
__device__ __align__(16) float g_agg0[NODE_PAD * 32];
__device__ __align__(16) float g_h1  [NODE_PAD * 64];
__device__ __align__(16) float g_agg1[NODE_PAD * 64];
__device__ __align__(16) float g_h2  [NODE_PAD * 64];
__device__ int g_deg[N_NODES];
__device__ int g_off[N_NODES + 1];
__device__ int g_cur[N_NODES];
__device__ int g_eidx[N_EDGES];
__device__ unsigned long long g_sstate[N_SCAN_BLKS];
__device__ int g_gstart[N_GRAPHS + 1];

// ---------------- fused prologue: edge count | bounds + node embed ----------
__global__ void __launch_bounds__(256) prologue_kernel(
    const int* __restrict__ dst,
    const int* __restrict__ batch,
    const int* __restrict__ x,
    const float* __restrict__ shape_emb,
    const float* __restrict__ color_emb,
    const float* __restrict__ W_node,
    const float* __restrict__ b_node)
{
    int tid = threadIdx.x;
    if (blockIdx.x < EB) {
        if (blockIdx.x == 0 && tid < N_SCAN_BLKS) g_sstate[tid] = 0ULL;
        int e = blockIdx.x * 256 + tid;
        if (e < N_EDGES) atomicAdd(&g_deg[dst[e]], 1);
        return;
    }
    int n = (blockIdx.x - EB) * 256 + tid;

    __shared__ float sW[16 * 32];
    __shared__ float sb[32];
    __shared__ float sS[64];
    __shared__ float sC[64];
    for (int i = tid; i < 16 * 32; i += 256) sW[i] = W_node[i];
    if (tid < 32) sb[tid] = b_node[tid];
    if (tid < 64) { sS[tid] = shape_emb[tid]; sC[tid] = color_emb[tid]; }
    __syncthreads();

    if (n >= N_NODES) return;

    // bounds (batch is sorted)
    {
        int b1 = batch[n];
        int b0 = (n == 0) ? -1 : batch[n - 1];
        for (int g = b0 + 1; g <= b1; g++) g_gstart[g] = n;
        if (n == N_NODES - 1)
            for (int g = b1 + 1; g <= N_GRAPHS; g++) g_gstart[g] = N_NODES;
    }

    // embedding
    int sh = x[2 * n];
    int co = x[2 * n + 1];
    float acc[32];
#pragma unroll
    for (int j = 0; j < 32; j++) acc[j] = sb[j];
#pragma unroll
    for (int k = 0; k < 8; k++) {
        float s = sS[sh * 8 + k];
        float c = sC[co * 8 + k];
#pragma unroll
        for (int j = 0; j < 32; j++)
            acc[j] += s * sW[k * 32 + j] + c * sW[(8 + k) * 32 + j];
    }
    float4* out = (float4*)&g_h0[(size_t)n * 32];
#pragma unroll
    for (int q = 0; q < 8; q++) {
        float4 v;
        v.x = fmaxf(acc[q * 4 + 0], 0.f);
        v.y = fmaxf(acc[q * 4 + 1], 0.f);
        v.z = fmaxf(acc[q * 4 + 2], 0.f);
        v.w = fmaxf(acc[q * 4 + 3], 0.f);
        out[q] = v;
    }
}

// ---------------- single-pass scan (decoupled lookback) ---------------------
// g_sstate[b] = (value << 2) | flag;  flag: 0=empty, 1=aggregate, 2=prefix.
__global__ void __launch_bounds__(SCAN_BLK) scan_kernel() {
    __shared__ int s[SCAN_BLK];
    __shared__ int sprefix;
    int bid = blockIdx.x, tid = threadIdx.x;
    int n = bid * SCAN_BLK + tid;
    int d = (n < N_NODES) ? g_deg[n] : 0;
    s[tid] = d;
    __syncthreads();
    for (int off = 1; off < SCAN_BLK; off <<= 1) {
        int v = (tid >= off) ? s[tid - off] : 0;
        __syncthreads();
        s[tid] += v;
        __syncthreads();
    }
    int agg = s[SCAN_BLK - 1];

    if (tid == 0) {
        if (bid == 0) {
            atomicExch(&g_sstate[0], ((unsigned long long)agg << 2) | 2ULL);
            sprefix = 0;
        } else {
            atomicExch(&g_sstate[bid], ((unsigned long long)agg << 2) | 1ULL);
            long long ex = 0;
            int p = bid - 1;
            for (;;) {
                unsigned long long v;
                do { v = atomicOr(&g_sstate[p], 0ULL); } while ((v & 3ULL) == 0ULL);
                ex += (long long)(v >> 2);
                if ((v & 3ULL) == 2ULL) break;
                p--;
            }
            atomicExch(&g_sstate[bid],
                       ((unsigned long long)(ex + agg) << 2) | 2ULL);
            sprefix = (int)ex;
        }
    }
    __syncthreads();
    int pre = sprefix;
    if (n < N_NODES) {
        int o = pre + s[tid] - d;   // exclusive
        g_off[n] = o;
        g_cur[n] = o;
    }
    if (bid == N_SCAN_BLKS - 1 && tid == SCAN_BLK - 1)
        g_off[N_NODES] = pre + agg;
}

// fill CSR; also restore the g_deg==0 invariant for the next call
__global__ void fill_kernel(const int* __restrict__ src, const int* __restrict__ dst) {
    int e = blockIdx.x * blockDim.x + threadIdx.x;
    if (e < N_NODES) g_deg[e] = 0;
    if (e >= N_EDGES) return;
    int d = dst[e];
    int pos = atomicAdd(&g_cur[d], 1);
    g_eidx[pos] = src[e];
}

// ---------------- gather aggregation (CSR, warp per node) -------------------
__global__ void __launch_bounds__(256) gather32_kernel() {
    int w = (blockIdx.x * 256 + threadIdx.x) >> 5;
    int lane = threadIdx.x & 31;
    if (w >= N_NODES) return;
    int s0 = g_off[w], s1 = g_off[w + 1];
    float acc = 0.f;
    int i = s0;
    for (; i + 3 < s1; i += 4) {
        int sa = __ldg(&g_eidx[i]);
        int sb = __ldg(&g_eidx[i + 1]);
        int sc = __ldg(&g_eidx[i + 2]);
        int sd = __ldg(&g_eidx[i + 3]);
        float va = g_h0[(size_t)sa * 32 + lane];
        float vb = g_h0[(size_t)sb * 32 + lane];
        float vc = g_h0[(size_t)sc * 32 + lane];
        float vd = g_h0[(size_t)sd * 32 + lane];
        acc += (va + vb) + (vc + vd);
    }
    for (; i < s1; i++)
        acc += g_h0[(size_t)__ldg(&g_eidx[i]) * 32 + lane];
    g_agg0[(size_t)w * 32 + lane] = acc;
}

__global__ void __launch_bounds__(256) gather64_kernel() {
    int w = (blockIdx.x * 256 + threadIdx.x) >> 5;
    int lane = threadIdx.x & 31;
    if (w >= N_NODES) return;
    int s0 = g_off[w], s1 = g_off[w + 1];
    float2 acc = make_float2(0.f, 0.f);
    int i = s0;
    for (; i + 3 < s1; i += 4) {
        int sa = __ldg(&g_eidx[i]);
        int sb = __ldg(&g_eidx[i + 1]);
        int sc = __ldg(&g_eidx[i + 2]);
        int sd = __ldg(&g_eidx[i + 3]);
        float2 va = ((const float2*)g_h1)[(size_t)sa * 32 + lane];
        float2 vb = ((const float2*)g_h1)[(size_t)sb * 32 + lane];
        float2 vc = ((const float2*)g_h1)[(size_t)sc * 32 + lane];
        float2 vd = ((const float2*)g_h1)[(size_t)sd * 32 + lane];
        acc.x += (va.x + vb.x) + (vc.x + vd.x);
        acc.y += (va.y + vb.y) + (vc.y + vd.y);
    }
    for (; i < s1; i++) {
        float2 va = ((const float2*)g_h1)[(size_t)__ldg(&g_eidx[i]) * 32 + lane];
        acc.x += va.x;
        acc.y += va.y;
    }
    ((float2*)g_agg1)[(size_t)w * 32 + lane] = acc;
}

// ---------------- tf32 tensor-core conv, smem-staged A ----------------------
// hout[M,64] = relu([agg|hin] @ [Wrel;Wroot] + b), K = 2*KIN.
// Block: 256 threads / 128 nodes. agg+hin tiles staged into smem with float4
// coalesced loads, MMA reads conflict-free (SAS = KIN+4 => banks 4*r4+c4;
// LDB = 72 => B-frag banks 8*c4+r4).
__device__ __forceinline__ uint32_t f2tf32(float f) {
    uint32_t u;
    asm("cvt.rna.tf32.f32 %0, %1;" : "=r"(u) : "f"(f));
    return u;
}

__device__ __forceinline__ void mma_tf32(float c[4],
                                         uint32_t a0, uint32_t a1, uint32_t a2, uint32_t a3,
                                         uint32_t b0, uint32_t b1) {
    asm volatile(
        "mma.sync.aligned.m16n8k8.row.col.f32.tf32.tf32.f32 "
        "{%0,%1,%2,%3}, {%4,%5,%6,%7}, {%8,%9}, {%0,%1,%2,%3};"
        : "+f"(c[0]), "+f"(c[1]), "+f"(c[2]), "+f"(c[3])
        : "r"(a0), "r"(a1), "r"(a2), "r"(a3), "r"(b0), "r"(b1));
}

template <int KIN, bool L1>
__global__ void __launch_bounds__(256) conv_tf32_kernel(
    const float* __restrict__ Wrel,
    const float* __restrict__ Wroot,
    const float* __restrict__ b)
{
    const float* agg  = L1 ? g_agg0 : g_agg1;
    const float* hin  = L1 ? g_h0   : g_h1;
    float*       hout = L1 ? g_h1   : g_h2;

    constexpr int K2 = 2 * KIN;
    constexpr int STEPS = K2 / 8;
    constexpr int LDB = 72;
    constexpr int SAS = KIN + 4;
    constexpr int QR  = KIN / 4;          // float4s per row

    extern __shared__ char smem[];
    uint32_t* sW = (uint32_t*)smem;                        // K2 * LDB
    float*    sb = (float*)(smem + (size_t)K2 * LDB * 4);  // 64
    float*    sA = sb + 64;                                // 128 * SAS
    float*    sH = sA + 128 * SAS;                         // 128 * SAS

    int tid = threadIdx.x;
    int base = blockIdx.x * 128;

    // weights -> smem (tf32 bits)
    for (int i = tid; i < K2 * 64; i += 256) {
        int k = i >> 6, n = i & 63;
        float v = (k < KIN) ? Wrel[k * 64 + n] : Wroot[(k - KIN) * 64 + n];
        sW[k * LDB + n] = f2tf32(v);
    }
    if (tid < 64) sb[tid] = b[tid];

    // stage A tiles with coalesced float4 loads
    for (int i = tid; i < 128 * QR; i += 256) {
        int row = i / QR, q = i % QR;
        float4 a4 = *(const float4*)(agg + (size_t)(base + row) * KIN + q * 4);
        float4 h4 = *(const float4*)(hin + (size_t)(base + row) * KIN + q * 4);
        *(float4*)&sA[row * SAS + q * 4] = a4;
        *(float4*)&sH[row * SAS + q * 4] = h4;
    }
    __syncthreads();

    int lane = tid & 31, wid = tid >> 5;
    int wm = wid >> 1, wn = wid & 1;
    int r4 = lane >> 2, c4 = lane & 3;
    int nl0 = wm * 32 + r4;

    float acc[2][4][4];
#pragma unroll
    for (int t = 0; t < 2; t++)
#pragma unroll
        for (int u = 0; u < 4; u++) {
            int col = wn * 32 + u * 8 + c4 * 2;
            acc[t][u][0] = sb[col];
            acc[t][u][1] = sb[col + 1];
            acc[t][u][2] = sb[col];
            acc[t][u][3] = sb[col + 1];
        }

#pragma unroll
    for (int s = 0; s < STEPS; s++) {
        const float* S = (s * 8 < KIN) ? sA : sH;
        int koff = s * 8 - ((s * 8 < KIN) ? 0 : KIN) + c4;

        uint32_t a[2][4];
#pragma unroll
        for (int t = 0; t < 2; t++) {
            const float* p0 = S + (nl0 + t * 16) * SAS + koff;
            const float* p8 = S + (nl0 + t * 16 + 8) * SAS + koff;
            a[t][0] = f2tf32(p0[0]);
            a[t][1] = f2tf32(p8[0]);
            a[t][2] = f2tf32(p0[4]);
            a[t][3] = f2tf32(p8[4]);
        }

        int krow = s * 8 + c4;
        uint32_t bf[4][2];
#pragma unroll
        for (int u = 0; u < 4; u++) {
            int col = wn * 32 + u * 8 + r4;
            bf[u][0] = sW[krow * LDB + col];
            bf[u][1] = sW[(krow + 4) * LDB + col];
        }

#pragma unroll
        for (int t = 0; t < 2; t++)
#pragma unroll
            for (int u = 0; u < 4; u++)
                mma_tf32(acc[t][u], a[t][0], a[t][1], a[t][2], a[t][3],
                         bf[u][0], bf[u][1]);
    }

#pragma unroll
    for (int t = 0; t < 2; t++) {
        int row = base + wm * 32 + t * 16 + r4;
#pragma unroll
        for (int u = 0; u < 4; u++) {
            int col = wn * 32 + u * 8 + c4 * 2;
            float2 lo = make_float2(fmaxf(acc[t][u][0], 0.f), fmaxf(acc[t][u][1], 0.f));
            float2 hi = make_float2(fmaxf(acc[t][u][2], 0.f), fmaxf(acc[t][u][3], 0.f));
            *(float2*)&hout[(size_t)row * 64 + col]       = lo;
            *(float2*)&hout[(size_t)(row + 8) * 64 + col] = hi;
        }
    }
}

// ---------------- fused mean-pool + classifier ------------------------------
__global__ void __launch_bounds__(64) poolcls_kernel(
    const float* __restrict__ W_cls,
    const float* __restrict__ b_cls,
    float* __restrict__ out)
{
    int g = blockIdx.x;
    int tid = threadIdx.x;
    int s = g_gstart[g], e = g_gstart[g + 1];
    float acc = 0.f;
    for (int n = s; n < e; n++) acc += g_h2[(size_t)n * 64 + tid];
    float cnt = fmaxf((float)(e - s), 1.0f);
    __shared__ float sp[64];
    sp[tid] = acc / cnt;
    __syncthreads();
    if (tid < 10) {
        float dot = b_cls[tid];
#pragma unroll 8
        for (int k = 0; k < 64; k++) dot += sp[k] * W_cls[k * 10 + tid];
        out[(size_t)g * 10 + tid] = dot;
    }
}

// ---------------- launch ------------------------------------------------------
extern "C" void kernel_launch(void* const* d_in, const int* in_sizes, int n_in,
                              void* d_out, int out_size)
{
    const int*   x         = (const int*)  d_in[0];
    const int*   edge_index= (const int*)  d_in[1];
    const int*   batch     = (const int*)  d_in[2];
    const float* shape_emb = (const float*)d_in[3];
    const float* color_emb = (const float*)d_in[4];
    const float* W_node    = (const float*)d_in[5];
    const float* b_node    = (const float*)d_in[6];
    const float* W1_rel    = (const float*)d_in[7];
    const float* W1_root   = (const float*)d_in[8];
    const float* b1        = (const float*)d_in[9];
    const float* W2_rel    = (const float*)d_in[10];
    const float* W2_root   = (const float*)d_in[11];
    const float* b2        = (const float*)d_in[12];
    const float* W_cls     = (const float*)d_in[13];
    const float* b_cls     = (const float*)d_in[14];
    float* out = (float*)d_out;

    const int* src = edge_index;            // edge_index[0, :]
    const int* dst = edge_index + N_EDGES;  // edge_index[1, :]

    // dynamic smem: sW(K2*72*4) + sb(64*4) + sA + sH (128*(KIN+4)*4 each)
    const int smem32 = 64 * 72 * 4 + 64 * 4 + 2 * 128 * 36 * 4;    // ~55 KB
    const int smem64 = 128 * 72 * 4 + 64 * 4 + 2 * 128 * 68 * 4;   // ~105 KB
    cudaFuncSetAttribute(conv_tf32_kernel<32, true>,
                         cudaFuncAttributeMaxDynamicSharedMemorySize, smem32);
    cudaFuncSetAttribute(conv_tf32_kernel<64, false>,
                         cudaFuncAttributeMaxDynamicSharedMemorySize, smem64);

    prologue_kernel<<<EB + NB, 256>>>(dst, batch, x, shape_emb, color_emb, W_node, b_node);
    scan_kernel<<<N_SCAN_BLKS, SCAN_BLK>>>();
    fill_kernel<<<(N_EDGES + 255) / 256, 256>>>(src, dst);

    gather32_kernel<<<(N_NODES * 32 + 255) / 256, 256>>>();
    conv_tf32_kernel<32, true><<<NODE_PAD / 128, 256, smem32>>>(W1_rel, W1_root, b1);

    gather64_kernel<<<(N_NODES * 32 + 255) / 256, 256>>>();
    conv_tf32_kernel<64, false><<<NODE_PAD / 128, 256, smem64>>>(W2_rel, W2_root, b2);

    poolcls_kernel<<<N_GRAPHS, 64>>>(W_cls, b_cls, out);
}

// round 7
// speedup vs baseline: 1.2512x; 1.0683x over previous
#include <cuda_runtime.h>
#include <cuda_bf16.h>
#include <cstdint>

#define N_NODES   100000
#define NODE_PAD  100096            // 782 * 128
#define N_EDGES   1000000
#define N_GRAPHS  1024
#define SCAN_BLK  512
#define N_SCAN_BLKS ((N_NODES + SCAN_BLK - 1) / SCAN_BLK)   // 196
#define EB ((N_EDGES + 255) / 256)  // edge blocks in prologue
#define NB ((N_NODES + 255) / 256)  // node blocks in prologue

// ---------------- scratch (device globals; zero-initialized at load) --------
// Invariants across calls:
//  - g_deg is zero on entry (BSS at load; fill_kernel re-zeroes after last use)
//  - g_sstate is zeroed by prologue block 0 each call, before the scan runs
//  - pad rows (>= N_NODES) of g_h0/g_agg0/g_agg1 are never written, stay zero
__device__ __align__(16) float g_h0  [NODE_PAD * 32];
__device__ __align__(16) float g_agg0[NODE_PAD * 32];
__device__ __align__(16) float g_h1  [NODE_PAD * 64];
__device__ __align__(16) float g_agg1[NODE_PAD * 64];
__device__ __align__(16) float g_h2  [NODE_PAD * 64];
__device__ int g_deg[N_NODES];
__device__ int g_off[N_NODES + 1];
__device__ int g_cur[N_NODES];
__device__ int g_eidx[N_EDGES];
__device__ unsigned long long g_sstate[N_SCAN_BLKS];
__device__ int g_gstart[N_GRAPHS + 1];

// ---------------- fused prologue: edge count | bounds + node embed ----------
__global__ void __launch_bounds__(256) prologue_kernel(
    const int* __restrict__ dst,
    const int* __restrict__ batch,
    const int* __restrict__ x,
    const float* __restrict__ shape_emb,
    const float* __restrict__ color_emb,
    const float* __restrict__ W_node,
    const float* __restrict__ b_node)
{
    int tid = threadIdx.x;
    if (blockIdx.x < EB) {
        if (blockIdx.x == 0 && tid < N_SCAN_BLKS) g_sstate[tid] = 0ULL;
        int e = blockIdx.x * 256 + tid;
        if (e < N_EDGES) atomicAdd(&g_deg[dst[e]], 1);
        return;
    }
    int n = (blockIdx.x - EB) * 256 + tid;

    __shared__ float sW[16 * 32];
    __shared__ float sb[32];
    __shared__ float sS[64];
    __shared__ float sC[64];
    for (int i = tid; i < 16 * 32; i += 256) sW[i] = W_node[i];
    if (tid < 32) sb[tid] = b_node[tid];
    if (tid < 64) { sS[tid] = shape_emb[tid]; sC[tid] = color_emb[tid]; }
    __syncthreads();

    if (n >= N_NODES) return;

    // bounds (batch is sorted)
    {
        int b1 = batch[n];
        int b0 = (n == 0) ? -1 : batch[n - 1];
        for (int g = b0 + 1; g <= b1; g++) g_gstart[g] = n;
        if (n == N_NODES - 1)
            for (int g = b1 + 1; g <= N_GRAPHS; g++) g_gstart[g] = N_NODES;
    }

    // embedding
    int sh = x[2 * n];
    int co = x[2 * n + 1];
    float acc[32];
#pragma unroll
    for (int j = 0; j < 32; j++) acc[j] = sb[j];
#pragma unroll
    for (int k = 0; k < 8; k++) {
        float s = sS[sh * 8 + k];
        float c = sC[co * 8 + k];
#pragma unroll
        for (int j = 0; j < 32; j++)
            acc[j] += s * sW[k * 32 + j] + c * sW[(8 + k) * 32 + j];
    }
    float4* out = (float4*)&g_h0[(size_t)n * 32];
#pragma unroll
    for (int q = 0; q < 8; q++) {
        float4 v;
        v.x = fmaxf(acc[q * 4 + 0], 0.f);
        v.y = fmaxf(acc[q * 4 + 1], 0.f);
        v.z = fmaxf(acc[q * 4 + 2], 0.f);
        v.w = fmaxf(acc[q * 4 + 3], 0.f);
        out[q] = v;
    }
}

// ---------------- single-pass scan (decoupled lookback) ---------------------
// g_sstate[b] = (value << 2) | flag;  flag: 0=empty, 1=aggregate, 2=prefix.
__global__ void __launch_bounds__(SCAN_BLK) scan_kernel() {
    __shared__ int s[SCAN_BLK];
    __shared__ int sprefix;
    int bid = blockIdx.x, tid = threadIdx.x;
    int n = bid * SCAN_BLK + tid;
    int d = (n < N_NODES) ? g_deg[n] : 0;
    s[tid] = d;
    __syncthreads();
    for (int off = 1; off < SCAN_BLK; off <<= 1) {
        int v = (tid >= off) ? s[tid - off] : 0;
        __syncthreads();
        s[tid] += v;
        __syncthreads();
    }
    int agg = s[SCAN_BLK - 1];

    if (tid == 0) {
        if (bid == 0) {
            atomicExch(&g_sstate[0], ((unsigned long long)agg << 2) | 2ULL);
            sprefix = 0;
        } else {
            atomicExch(&g_sstate[bid], ((unsigned long long)agg << 2) | 1ULL);
            long long ex = 0;
            int p = bid - 1;
            for (;;) {
                unsigned long long v;
                do { v = atomicOr(&g_sstate[p], 0ULL); } while ((v & 3ULL) == 0ULL);
                ex += (long long)(v >> 2);
                if ((v & 3ULL) == 2ULL) break;
                p--;
            }
            atomicExch(&g_sstate[bid],
                       ((unsigned long long)(ex + agg) << 2) | 2ULL);
            sprefix = (int)ex;
        }
    }
    __syncthreads();
    int pre = sprefix;
    if (n < N_NODES) {
        int o = pre + s[tid] - d;   // exclusive
        g_off[n] = o;
        g_cur[n] = o;
    }
    if (bid == N_SCAN_BLKS - 1 && tid == SCAN_BLK - 1)
        g_off[N_NODES] = pre + agg;
}

// fill CSR; also restore the g_deg==0 invariant for the next call
__global__ void fill_kernel(const int* __restrict__ src, const int* __restrict__ dst) {
    int e = blockIdx.x * blockDim.x + threadIdx.x;
    if (e < N_NODES) g_deg[e] = 0;
    if (e >= N_EDGES) return;
    int d = dst[e];
    int pos = atomicAdd(&g_cur[d], 1);
    g_eidx[pos] = src[e];
}

// ---------------- gather aggregation (warp per node, 4 edges in flight) -----
// Lane split: g = lane>>3 (edge subgroup 0..3), q = lane&7 (float4 chunk).
// Each subgroup loads full rows as float4s; butterfly shfl (xor8,16) combines.
__global__ void __launch_bounds__(256) gather32_kernel() {
    int w = (blockIdx.x * 256 + threadIdx.x) >> 5;
    int lane = threadIdx.x & 31;
    if (w >= N_NODES) return;
    int g = lane >> 3;
    unsigned q4 = (unsigned)(lane & 7) * 4u;
    int s0 = g_off[w], s1 = g_off[w + 1];
    float4 acc = make_float4(0.f, 0.f, 0.f, 0.f);
    for (int i = s0 + g; i < s1; i += 4) {
        unsigned idx = (unsigned)__ldg(&g_eidx[i]);
        float4 v = *(const float4*)(g_h0 + idx * 32u + q4);
        acc.x += v.x; acc.y += v.y; acc.z += v.z; acc.w += v.w;
    }
#pragma unroll
    for (int off = 8; off <= 16; off <<= 1) {
        acc.x += __shfl_xor_sync(0xffffffff, acc.x, off);
        acc.y += __shfl_xor_sync(0xffffffff, acc.y, off);
        acc.z += __shfl_xor_sync(0xffffffff, acc.z, off);
        acc.w += __shfl_xor_sync(0xffffffff, acc.w, off);
    }
    if (lane < 8)
        *(float4*)(g_agg0 + (unsigned)w * 32u + q4) = acc;
}

__global__ void __launch_bounds__(256) gather64_kernel() {
    int w = (blockIdx.x * 256 + threadIdx.x) >> 5;
    int lane = threadIdx.x & 31;
    if (w >= N_NODES) return;
    int g = lane >> 3;
    unsigned q4 = (unsigned)(lane & 7) * 4u;
    int s0 = g_off[w], s1 = g_off[w + 1];
    float4 a0 = make_float4(0.f, 0.f, 0.f, 0.f);
    float4 a1 = make_float4(0.f, 0.f, 0.f, 0.f);
    for (int i = s0 + g; i < s1; i += 4) {
        unsigned idx = (unsigned)__ldg(&g_eidx[i]);
        const float* row = g_h1 + idx * 64u;
        float4 v0 = *(const float4*)(row + q4);
        float4 v1 = *(const float4*)(row + 32u + q4);
        a0.x += v0.x; a0.y += v0.y; a0.z += v0.z; a0.w += v0.w;
        a1.x += v1.x; a1.y += v1.y; a1.z += v1.z; a1.w += v1.w;
    }
#pragma unroll
    for (int off = 8; off <= 16; off <<= 1) {
        a0.x += __shfl_xor_sync(0xffffffff, a0.x, off);
        a0.y += __shfl_xor_sync(0xffffffff, a0.y, off);
        a0.z += __shfl_xor_sync(0xffffffff, a0.z, off);
        a0.w += __shfl_xor_sync(0xffffffff, a0.w, off);
        a1.x += __shfl_xor_sync(0xffffffff, a1.x, off);
        a1.y += __shfl_xor_sync(0xffffffff, a1.y, off);
        a1.z += __shfl_xor_sync(0xffffffff, a1.z, off);
        a1.w += __shfl_xor_sync(0xffffffff, a1.w, off);
    }
    if (lane < 8) {
        float* orow = g_agg1 + (unsigned)w * 64u;
        *(float4*)(orow + q4)       = a0;
        *(float4*)(orow + 32u + q4) = a1;
    }
}

// ---------------- tf32 tensor-core conv, smem-staged A ----------------------
__device__ __forceinline__ uint32_t f2tf32(float f) {
    uint32_t u;
    asm("cvt.rna.tf32.f32 %0, %1;" : "=r"(u) : "f"(f));
    return u;
}

__device__ __forceinline__ void mma_tf32(float c[4],
                                         uint32_t a0, uint32_t a1, uint32_t a2, uint32_t a3,
                                         uint32_t b0, uint32_t b1) {
    asm volatile(
        "mma.sync.aligned.m16n8k8.row.col.f32.tf32.tf32.f32 "
        "{%0,%1,%2,%3}, {%4,%5,%6,%7}, {%8,%9}, {%0,%1,%2,%3};"
        : "+f"(c[0]), "+f"(c[1]), "+f"(c[2]), "+f"(c[3])
        : "r"(a0), "r"(a1), "r"(a2), "r"(a3), "r"(b0), "r"(b1));
}

template <int KIN, bool L1>
__global__ void __launch_bounds__(256) conv_tf32_kernel(
    const float* __restrict__ Wrel,
    const float* __restrict__ Wroot,
    const float* __restrict__ b)
{
    const float* agg  = L1 ? g_agg0 : g_agg1;
    const float* hin  = L1 ? g_h0   : g_h1;
    float*       hout = L1 ? g_h1   : g_h2;

    constexpr int K2 = 2 * KIN;
    constexpr int STEPS = K2 / 8;
    constexpr int LDB = 72;
    constexpr int SAS = KIN + 4;
    constexpr int QR  = KIN / 4;          // float4s per row

    extern __shared__ char smem[];
    uint32_t* sW = (uint32_t*)smem;                        // K2 * LDB
    float*    sb = (float*)(smem + (size_t)K2 * LDB * 4);  // 64
    float*    sA = sb + 64;                                // 128 * SAS
    float*    sH = sA + 128 * SAS;                         // 128 * SAS

    int tid = threadIdx.x;
    int base = blockIdx.x * 128;

    // weights -> smem (tf32 bits)
    for (int i = tid; i < K2 * 64; i += 256) {
        int k = i >> 6, n = i & 63;
        float v = (k < KIN) ? Wrel[k * 64 + n] : Wroot[(k - KIN) * 64 + n];
        sW[k * LDB + n] = f2tf32(v);
    }
    if (tid < 64) sb[tid] = b[tid];

    // stage A tiles with coalesced float4 loads
    for (int i = tid; i < 128 * QR; i += 256) {
        int row = i / QR, q = i % QR;
        float4 a4 = *(const float4*)(agg + (size_t)(base + row) * KIN + q * 4);
        float4 h4 = *(const float4*)(hin + (size_t)(base + row) * KIN + q * 4);
        *(float4*)&sA[row * SAS + q * 4] = a4;
        *(float4*)&sH[row * SAS + q * 4] = h4;
    }
    __syncthreads();

    int lane = tid & 31, wid = tid >> 5;
    int wm = wid >> 1, wn = wid & 1;
    int r4 = lane >> 2, c4 = lane & 3;
    int nl0 = wm * 32 + r4;

    float acc[2][4][4];
#pragma unroll
    for (int t = 0; t < 2; t++)
#pragma unroll
        for (int u = 0; u < 4; u++) {
            int col = wn * 32 + u * 8 + c4 * 2;
            acc[t][u][0] = sb[col];
            acc[t][u][1] = sb[col + 1];
            acc[t][u][2] = sb[col];
            acc[t][u][3] = sb[col + 1];
        }

#pragma unroll
    for (int s = 0; s < STEPS; s++) {
        const float* S = (s * 8 < KIN) ? sA : sH;
        int koff = s * 8 - ((s * 8 < KIN) ? 0 : KIN) + c4;

        uint32_t a[2][4];
#pragma unroll
        for (int t = 0; t < 2; t++) {
            const float* p0 = S + (nl0 + t * 16) * SAS + koff;
            const float* p8 = S + (nl0 + t * 16 + 8) * SAS + koff;
            a[t][0] = f2tf32(p0[0]);
            a[t][1] = f2tf32(p8[0]);
            a[t][2] = f2tf32(p0[4]);
            a[t][3] = f2tf32(p8[4]);
        }

        int krow = s * 8 + c4;
        uint32_t bf[4][2];
#pragma unroll
        for (int u = 0; u < 4; u++) {
            int col = wn * 32 + u * 8 + r4;
            bf[u][0] = sW[krow * LDB + col];
            bf[u][1] = sW[(krow + 4) * LDB + col];
        }

#pragma unroll
        for (int t = 0; t < 2; t++)
#pragma unroll
            for (int u = 0; u < 4; u++)
                mma_tf32(acc[t][u], a[t][0], a[t][1], a[t][2], a[t][3],
                         bf[u][0], bf[u][1]);
    }

#pragma unroll
    for (int t = 0; t < 2; t++) {
        int row = base + wm * 32 + t * 16 + r4;
#pragma unroll
        for (int u = 0; u < 4; u++) {
            int col = wn * 32 + u * 8 + c4 * 2;
            float2 lo = make_float2(fmaxf(acc[t][u][0], 0.f), fmaxf(acc[t][u][1], 0.f));
            float2 hi = make_float2(fmaxf(acc[t][u][2], 0.f), fmaxf(acc[t][u][3], 0.f));
            *(float2*)&hout[(size_t)row * 64 + col]       = lo;
            *(float2*)&hout[(size_t)(row + 8) * 64 + col] = hi;
        }
    }
}

// ---------------- fused mean-pool + classifier ------------------------------
__global__ void __launch_bounds__(64) poolcls_kernel(
    const float* __restrict__ W_cls,
    const float* __restrict__ b_cls,
    float* __restrict__ out)
{
    int g = blockIdx.x;
    int tid = threadIdx.x;
    int s = g_gstart[g], e = g_gstart[g + 1];
    float acc = 0.f;
    for (int n = s; n < e; n++) acc += g_h2[(size_t)n * 64 + tid];
    float cnt = fmaxf((float)(e - s), 1.0f);
    __shared__ float sp[64];
    sp[tid] = acc / cnt;
    __syncthreads();
    if (tid < 10) {
        float dot = b_cls[tid];
#pragma unroll 8
        for (int k = 0; k < 64; k++) dot += sp[k] * W_cls[k * 10 + tid];
        out[(size_t)g * 10 + tid] = dot;
    }
}

// ---------------- launch ------------------------------------------------------
extern "C" void kernel_launch(void* const* d_in, const int* in_sizes, int n_in,
                              void* d_out, int out_size)
{
    const int*   x         = (const int*)  d_in[0];
    const int*   edge_index= (const int*)  d_in[1];
    const int*   batch     = (const int*)  d_in[2];
    const float* shape_emb = (const float*)d_in[3];
    const float* color_emb = (const float*)d_in[4];
    const float* W_node    = (const float*)d_in[5];
    const float* b_node    = (const float*)d_in[6];
    const float* W1_rel    = (const float*)d_in[7];
    const float* W1_root   = (const float*)d_in[8];
    const float* b1        = (const float*)d_in[9];
    const float* W2_rel    = (const float*)d_in[10];
    const float* W2_root   = (const float*)d_in[11];
    const float* b2        = (const float*)d_in[12];
    const float* W_cls     = (const float*)d_in[13];
    const float* b_cls     = (const float*)d_in[14];
    float* out = (float*)d_out;

    const int* src = edge_index;            // edge_index[0, :]
    const int* dst = edge_index + N_EDGES;  // edge_index[1, :]

    // dynamic smem: sW(K2*72*4) + sb(64*4) + sA + sH (128*(KIN+4)*4 each)
    const int smem32 = 64 * 72 * 4 + 64 * 4 + 2 * 128 * 36 * 4;    // ~55 KB
    const int smem64 = 128 * 72 * 4 + 64 * 4 + 2 * 128 * 68 * 4;   // ~105 KB
    cudaFuncSetAttribute(conv_tf32_kernel<32, true>,
                         cudaFuncAttributeMaxDynamicSharedMemorySize, smem32);
    cudaFuncSetAttribute(conv_tf32_kernel<64, false>,
                         cudaFuncAttributeMaxDynamicSharedMemorySize, smem64);

    prologue_kernel<<<EB + NB, 256>>>(dst, batch, x, shape_emb, color_emb, W_node, b_node);
    scan_kernel<<<N_SCAN_BLKS, SCAN_BLK>>>();
    fill_kernel<<<(N_EDGES + 255) / 256, 256>>>(src, dst);

    gather32_kernel<<<(N_NODES * 32 + 255) / 256, 256>>>();
    conv_tf32_kernel<32, true><<<NODE_PAD / 128, 256, smem32>>>(W1_rel, W1_root, b1);

    gather64_kernel<<<(N_NODES * 32 + 255) / 256, 256>>>();
    conv_tf32_kernel<64, false><<<NODE_PAD / 128, 256, smem64>>>(W2_rel, W2_root, b2);

    poolcls_kernel<<<N_GRAPHS, 64>>>(W_cls, b_cls, out);
}

// round 9
// speedup vs baseline: 1.3800x; 1.1029x over previous
#include <cuda_runtime.h>
#include <cuda_bf16.h>
#include <cstdint>

#define N_NODES   100000
#define NODE_PAD  100096            // 782 * 128
#define N_EDGES   1000000
#define N_GRAPHS  1024
#define SCAN_BLK  512
#define N_SCAN_BLKS ((N_NODES + SCAN_BLK - 1) / SCAN_BLK)   // 196
#define EB ((N_EDGES + 255) / 256)  // 3907 edge blocks in prologue
#define NB ((N_NODES + 255) / 256)  // 391 node blocks in prologue
#define SRC_MASK ((1u << 20) - 1u)

// ---------------- scratch (device globals; zero-initialized at load) --------
// Invariants across calls:
//  - g_deg is zero on entry (BSS at load; fill_kernel re-zeroes after last use)
//  - g_sstate is zeroed by prologue block 0 each call, before the scan runs
//  - pad rows (>= N_NODES) of g_h1/g_agg1 are never written, stay zero
__device__ __align__(16) float g_h1  [NODE_PAD * 64];
__device__ __align__(16) float g_agg1[NODE_PAD * 64];
__device__ __align__(16) float g_h2  [NODE_PAD * 64];
__device__ __align__(16) float g_tabRel  [64 * 64];   // relu_table @ W1_rel
__device__ __align__(16) float g_tabRootB[64 * 64];   // relu_table @ W1_root + b1
__device__ int g_ncls[N_NODES];
__device__ int g_deg[N_NODES];
__device__ int g_off[N_NODES + 1];
__device__ int g_cur[N_NODES];
__device__ unsigned g_eidx[N_EDGES];                  // src | (cls << 20)
__device__ unsigned long long g_sstate[N_SCAN_BLKS];
__device__ int g_gstart[N_GRAPHS + 1];

// ---------------- fused prologue: edge count | class+bounds | tables --------
__global__ void __launch_bounds__(256) prologue_kernel(
    const int* __restrict__ dst,
    const int* __restrict__ batch,
    const int* __restrict__ x,
    const float* __restrict__ shape_emb,
    const float* __restrict__ color_emb,
    const float* __restrict__ W_node,
    const float* __restrict__ b_node,
    const float* __restrict__ W1_rel,
    const float* __restrict__ W1_root,
    const float* __restrict__ b1)
{
    __shared__ float sWn[16 * 32];
    __shared__ float sS[64], sC[64], sbn[32], sb1[64];
    __shared__ float sT[64 * 32];
    __shared__ float sW1r[32 * 64], sW1o[32 * 64];

    int tid = threadIdx.x;
    int bid = blockIdx.x;
    if (bid < EB) {
        // role 1: degree count (+ block 0 resets scan state for this call)
        if (bid == 0 && tid < N_SCAN_BLKS) g_sstate[tid] = 0ULL;
        int e = bid * 256 + tid;
        if (e < N_EDGES) atomicAdd(&g_deg[dst[e]], 1);
        return;
    }
    if (bid < EB + NB) {
        // role 2: node class + graph bounds (batch is sorted)
        int n = (bid - EB) * 256 + tid;
        if (n >= N_NODES) return;
        int b1v = batch[n];
        int b0v = (n == 0) ? -1 : batch[n - 1];
        for (int g = b0v + 1; g <= b1v; g++) g_gstart[g] = n;
        if (n == N_NODES - 1)
            for (int g = b1v + 1; g <= N_GRAPHS; g++) g_gstart[g] = N_NODES;
        g_ncls[n] = x[2 * n] * 8 + x[2 * n + 1];
        return;
    }
    // role 3: build layer-1 class tables (single block)
    for (int i = tid; i < 512; i += 256) sWn[i] = W_node[i];
    if (tid < 64) { sS[tid] = shape_emb[tid]; sC[tid] = color_emb[tid]; sb1[tid] = b1[tid]; }
    if (tid < 32) sbn[tid] = b_node[tid];
    for (int i = tid; i < 2048; i += 256) { sW1r[i] = W1_rel[i]; sW1o[i] = W1_root[i]; }
    __syncthreads();
    // relu table rows: 64 classes x 32 cols (4 threads per class, 8 cols each)
    {
        int c = tid >> 2, q = tid & 3;
        int sh = c >> 3, co = c & 7;
        for (int j = q * 8; j < q * 8 + 8; j++) {
            float a = sbn[j];
#pragma unroll
            for (int k = 0; k < 8; k++)
                a += sS[sh * 8 + k] * sWn[k * 32 + j]
                   + sC[co * 8 + k] * sWn[(8 + k) * 32 + j];
            sT[c * 32 + j] = fmaxf(a, 0.f);
        }
    }
    __syncthreads();
    for (int i = tid; i < 4096; i += 256) {
        int c = i >> 6, j = i & 63;
        float ar = 0.f, ao = sb1[j];
#pragma unroll
        for (int k = 0; k < 32; k++) {
            float t = sT[c * 32 + k];
            ar += t * sW1r[k * 64 + j];
            ao += t * sW1o[k * 64 + j];
        }
        g_tabRel[i]   = ar;
        g_tabRootB[i] = ao;
    }
}

// ---------------- single-pass scan (decoupled lookback) ---------------------
__global__ void __launch_bounds__(SCAN_BLK) scan_kernel() {
    __shared__ int s[SCAN_BLK];
    __shared__ int sprefix;
    int bid = blockIdx.x, tid = threadIdx.x;
    int n = bid * SCAN_BLK + tid;
    int d = (n < N_NODES) ? g_deg[n] : 0;
    s[tid] = d;
    __syncthreads();
    for (int off = 1; off < SCAN_BLK; off <<= 1) {
        int v = (tid >= off) ? s[tid - off] : 0;
        __syncthreads();
        s[tid] += v;
        __syncthreads();
    }
    int agg = s[SCAN_BLK - 1];

    if (tid == 0) {
        if (bid == 0) {
            atomicExch(&g_sstate[0], ((unsigned long long)agg << 2) | 2ULL);
            sprefix = 0;
        } else {
            atomicExch(&g_sstate[bid], ((unsigned long long)agg << 2) | 1ULL);
            long long ex = 0;
            int p = bid - 1;
            for (;;) {
                unsigned long long v;
                do { v = atomicOr(&g_sstate[p], 0ULL); } while ((v & 3ULL) == 0ULL);
                ex += (long long)(v >> 2);
                if ((v & 3ULL) == 2ULL) break;
                p--;
            }
            atomicExch(&g_sstate[bid],
                       ((unsigned long long)(ex + agg) << 2) | 2ULL);
            sprefix = (int)ex;
        }
    }
    __syncthreads();
    int pre = sprefix;
    if (n < N_NODES) {
        int o = pre + s[tid] - d;   // exclusive
        g_off[n] = o;
        g_cur[n] = o;
    }
    if (bid == N_SCAN_BLKS - 1 && tid == SCAN_BLK - 1)
        g_off[N_NODES] = pre + agg;
}

// fill CSR (packed src|cls); restore g_deg==0 invariant for the next call
__global__ void fill_kernel(const int* __restrict__ src, const int* __restrict__ dst) {
    int e = blockIdx.x * blockDim.x + threadIdx.x;
    if (e < N_NODES) g_deg[e] = 0;
    if (e >= N_EDGES) return;
    int d = dst[e];
    int s = src[e];
    int pos = atomicAdd(&g_cur[d], 1);
    g_eidx[pos] = (unsigned)s | ((unsigned)g_ncls[s] << 20);
}

// ---------------- layer 1: h1 = relu(sum tabRel[cls] + tabRootB[cls_v]) -----
// Persistent-style: table loaded to smem once per block; warp per node,
// grid-stride. Edge classes prefetched 32-at-a-time (coalesced), broadcast
// per edge via shfl, rows summed from smem (lane owns 2 of 64 cols).
__global__ void __launch_bounds__(256) layer1_kernel() {
    __shared__ float sR[4096];
    __shared__ float sO[4096];
    int tid = threadIdx.x;
    for (int i = tid * 4; i < 4096; i += 1024) {
        *(float4*)&sR[i] = *(const float4*)&g_tabRel[i];
        *(float4*)&sO[i] = *(const float4*)&g_tabRootB[i];
    }
    __syncthreads();

    int lane = tid & 31, wid = tid >> 5;
    int warpsTotal = gridDim.x * 8;
    for (int node = blockIdx.x * 8 + wid; node < N_NODES; node += warpsTotal) {
        int s0 = g_off[node], s1 = g_off[node + 1];
        int cv = g_ncls[node];
        float2 acc = *(const float2*)&sO[cv * 64 + 2 * lane];
        for (int i = s0; i < s1; i += 32) {
            unsigned pv = (i + lane < s1) ? g_eidx[i + lane] : 0u;
            int cnt = s1 - i;
            if (cnt > 32) cnt = 32;
            for (int j = 0; j < cnt; j++) {
                unsigned c = __shfl_sync(0xffffffff, pv, j) >> 20;
                float2 v = *(const float2*)&sR[c * 64 + 2 * lane];
                acc.x += v.x;
                acc.y += v.y;
            }
        }
        acc.x = fmaxf(acc.x, 0.f);
        acc.y = fmaxf(acc.y, 0.f);
        *(float2*)&g_h1[(size_t)node * 64 + 2 * lane] = acc;
    }
}

// ---------------- gather64: agg1[v] = sum h1[src] (prefetch + shfl) ---------
__global__ void __launch_bounds__(256) gather64_kernel() {
    int w = (blockIdx.x * 256 + threadIdx.x) >> 5;
    int lane = threadIdx.x & 31;
    if (w >= N_NODES) return;
    int s0 = g_off[w], s1 = g_off[w + 1];
    float2 acc = make_float2(0.f, 0.f);
    for (int i = s0; i < s1; i += 32) {
        unsigned pv = (i + lane < s1) ? g_eidx[i + lane] : 0u;
        int cnt = s1 - i;
        if (cnt > 32) cnt = 32;
        for (int j = 0; j < cnt; j++) {
            unsigned idx = __shfl_sync(0xffffffff, pv, j) & SRC_MASK;
            float2 v = *(const float2*)(g_h1 + idx * 64u + 2u * lane);
            acc.x += v.x;
            acc.y += v.y;
        }
    }
    *(float2*)(g_agg1 + (unsigned)w * 64u + 2u * lane) = acc;
}

// ---------------- tf32 tensor-core conv (layer 2), smem-staged A ------------
__device__ __forceinline__ uint32_t f2tf32(float f) {
    uint32_t u;
    asm("cvt.rna.tf32.f32 %0, %1;" : "=r"(u) : "f"(f));
    return u;
}

__device__ __forceinline__ void mma_tf32(float c[4],
                                         uint32_t a0, uint32_t a1, uint32_t a2, uint32_t a3,
                                         uint32_t b0, uint32_t b1) {
    asm volatile(
        "mma.sync.aligned.m16n8k8.row.col.f32.tf32.tf32.f32 "
        "{%0,%1,%2,%3}, {%4,%5,%6,%7}, {%8,%9}, {%0,%1,%2,%3};"
        : "+f"(c[0]), "+f"(c[1]), "+f"(c[2]), "+f"(c[3])
        : "r"(a0), "r"(a1), "r"(a2), "r"(a3), "r"(b0), "r"(b1));
}

__global__ void __launch_bounds__(256) conv2_kernel(
    const float* __restrict__ Wrel,
    const float* __restrict__ Wroot,
    const float* __restrict__ b)
{
    constexpr int KIN = 64;
    constexpr int K2 = 128;
    constexpr int STEPS = 16;
    constexpr int LDB = 72;
    constexpr int SAS = KIN + 4;
    constexpr int QR  = KIN / 4;

    extern __shared__ char smem[];
    uint32_t* sW = (uint32_t*)smem;                        // K2 * LDB
    float*    sb = (float*)(smem + (size_t)K2 * LDB * 4);  // 64
    float*    sA = sb + 64;                                // 128 * SAS
    float*    sH = sA + 128 * SAS;                         // 128 * SAS

    int tid = threadIdx.x;
    int base = blockIdx.x * 128;

    for (int i = tid; i < K2 * 64; i += 256) {
        int k = i >> 6, n = i & 63;
        float v = (k < KIN) ? Wrel[k * 64 + n] : Wroot[(k - KIN) * 64 + n];
        sW[k * LDB + n] = f2tf32(v);
    }
    if (tid < 64) sb[tid] = b[tid];

    for (int i = tid; i < 128 * QR; i += 256) {
        int row = i / QR, q = i % QR;
        float4 a4 = *(const float4*)(g_agg1 + (size_t)(base + row) * KIN + q * 4);
        float4 h4 = *(const float4*)(g_h1   + (size_t)(base + row) * KIN + q * 4);
        *(float4*)&sA[row * SAS + q * 4] = a4;
        *(float4*)&sH[row * SAS + q * 4] = h4;
    }
    __syncthreads();

    int lane = tid & 31, wid = tid >> 5;
    int wm = wid >> 1, wn = wid & 1;
    int r4 = lane >> 2, c4 = lane & 3;
    int nl0 = wm * 32 + r4;

    float acc[2][4][4];
#pragma unroll
    for (int t = 0; t < 2; t++)
#pragma unroll
        for (int u = 0; u < 4; u++) {
            int col = wn * 32 + u * 8 + c4 * 2;
            acc[t][u][0] = sb[col];
            acc[t][u][1] = sb[col + 1];
            acc[t][u][2] = sb[col];
            acc[t][u][3] = sb[col + 1];
        }

#pragma unroll
    for (int s = 0; s < STEPS; s++) {
        const float* S = (s * 8 < KIN) ? sA : sH;
        int koff = s * 8 - ((s * 8 < KIN) ? 0 : KIN) + c4;

        uint32_t a[2][4];
#pragma unroll
        for (int t = 0; t < 2; t++) {
            const float* p0 = S + (nl0 + t * 16) * SAS + koff;
            const float* p8 = S + (nl0 + t * 16 + 8) * SAS + koff;
            a[t][0] = f2tf32(p0[0]);
            a[t][1] = f2tf32(p8[0]);
            a[t][2] = f2tf32(p0[4]);
            a[t][3] = f2tf32(p8[4]);
        }

        int krow = s * 8 + c4;
        uint32_t bf[4][2];
#pragma unroll
        for (int u = 0; u < 4; u++) {
            int col = wn * 32 + u * 8 + r4;
            bf[u][0] = sW[krow * LDB + col];
            bf[u][1] = sW[(krow + 4) * LDB + col];
        }

#pragma unroll
        for (int t = 0; t < 2; t++)
#pragma unroll
            for (int u = 0; u < 4; u++)
                mma_tf32(acc[t][u], a[t][0], a[t][1], a[t][2], a[t][3],
                         bf[u][0], bf[u][1]);
    }

#pragma unroll
    for (int t = 0; t < 2; t++) {
        int row = base + wm * 32 + t * 16 + r4;
#pragma unroll
        for (int u = 0; u < 4; u++) {
            int col = wn * 32 + u * 8 + c4 * 2;
            float2 lo = make_float2(fmaxf(acc[t][u][0], 0.f), fmaxf(acc[t][u][1], 0.f));
            float2 hi = make_float2(fmaxf(acc[t][u][2], 0.f), fmaxf(acc[t][u][3], 0.f));
            *(float2*)&g_h2[(size_t)row * 64 + col]       = lo;
            *(float2*)&g_h2[(size_t)(row + 8) * 64 + col] = hi;
        }
    }
}

// ---------------- fused mean-pool + classifier ------------------------------
__global__ void __launch_bounds__(64) poolcls_kernel(
    const float* __restrict__ W_cls,
    const float* __restrict__ b_cls,
    float* __restrict__ out)
{
    int g = blockIdx.x;
    int tid = threadIdx.x;
    int s = g_gstart[g], e = g_gstart[g + 1];
    float acc = 0.f;
    for (int n = s; n < e; n++) acc += g_h2[(size_t)n * 64 + tid];
    float cnt = fmaxf((float)(e - s), 1.0f);
    __shared__ float sp[64];
    sp[tid] = acc / cnt;
    __syncthreads();
    if (tid < 10) {
        float dot = b_cls[tid];
#pragma unroll 8
        for (int k = 0; k < 64; k++) dot += sp[k] * W_cls[k * 10 + tid];
        out[(size_t)g * 10 + tid] = dot;
    }
}

// ---------------- launch ------------------------------------------------------
extern "C" void kernel_launch(void* const* d_in, const int* in_sizes, int n_in,
                              void* d_out, int out_size)
{
    const int*   x         = (const int*)  d_in[0];
    const int*   edge_index= (const int*)  d_in[1];
    const int*   batch     = (const int*)  d_in[2];
    const float* shape_emb = (const float*)d_in[3];
    const float* color_emb = (const float*)d_in[4];
    const float* W_node    = (const float*)d_in[5];
    const float* b_node    = (const float*)d_in[6];
    const float* W1_rel    = (const float*)d_in[7];
    const float* W1_root   = (const float*)d_in[8];
    const float* b1        = (const float*)d_in[9];
    const float* W2_rel    = (const float*)d_in[10];
    const float* W2_root   = (const float*)d_in[11];
    const float* b2        = (const float*)d_in[12];
    const float* W_cls     = (const float*)d_in[13];
    const float* b_cls     = (const float*)d_in[14];
    float* out = (float*)d_out;

    const int* src = edge_index;            // edge_index[0, :]
    const int* dst = edge_index + N_EDGES;  // edge_index[1, :]

    const int smem64 = 128 * 72 * 4 + 64 * 4 + 2 * 128 * 68 * 4;   // ~105 KB
    cudaFuncSetAttribute(conv2_kernel,
                         cudaFuncAttributeMaxDynamicSharedMemorySize, smem64);

    prologue_kernel<<<EB + NB + 1, 256>>>(dst, batch, x, shape_emb, color_emb,
                                          W_node, b_node, W1_rel, W1_root, b1);
    scan_kernel<<<N_SCAN_BLKS, SCAN_BLK>>>();
    fill_kernel<<<(N_EDGES + 255) / 256, 256>>>(src, dst);

    layer1_kernel<<<592, 256>>>();
    gather64_kernel<<<(N_NODES + 7) / 8, 256>>>();
    conv2_kernel<<<NODE_PAD / 128, 256, smem64>>>(W2_rel, W2_root, b2);

    poolcls_kernel<<<N_GRAPHS, 64>>>(W_cls, b_cls, out);
}